// round 6
// baseline (speedup 1.0000x reference)
#include <cuda_runtime.h>
#include <cstdint>

// ---------------- problem constants ----------------
#define NQ       512          // batch (queries)
#define NA       100000       // number of stored addresses
#define KDIM     1024
#define CDIM     1024
#define NROWPAD  100096       // NA padded to multiple of 128
#define MTILES   6256         // NROWPAD / 16
#define NKS      16           // k-steps of 64 (s4 mma k64)
#define NCTA     1564         // (NROWPAD/128) * 2 N-passes
#define PAIR_CAP (1u<<20)

// ---------------- device globals (static, no runtime alloc) ----------------
// A fragments (s4): [mtile(6256)][kstep(16)][lane(32)][reg(4)] uint32 (8 nibbles each)
__device__ unsigned g_afrag[MTILES * NKS * 32 * 4];
// B fragments (s4): [pair(32)][kstep(16)][lane(32)][reg(4)]  (pair = 2 n8-tiles)
__device__ unsigned g_bfrag[32 * NKS * 32 * 4];
__device__ unsigned g_npairs;
__device__ unsigned g_pairs[PAIR_CAP];

// ---------------- IMMA: m16n8k64 s4*s4 -> s32 ----------------
__device__ __forceinline__ void imma(int* c, const uint4& a, unsigned b0, unsigned b1) {
    asm volatile(
        "mma.sync.aligned.m16n8k64.row.col.s32.s4.s4.s32 "
        "{%0,%1,%2,%3}, {%4,%5,%6,%7}, {%8,%9}, {%0,%1,%2,%3};"
        : "+r"(c[0]), "+r"(c[1]), "+r"(c[2]), "+r"(c[3])
        : "r"(a.x), "r"(a.y), "r"(a.z), "r"(a.w), "r"(b0), "r"(b1));
}

// pack 8 floats (each +1/-1) into 8 signed nibbles
__device__ __forceinline__ unsigned pack8(const float4& x, const float4& y) {
    unsigned r;
    r  = ((unsigned)((int)x.x & 0xF));
    r |= ((unsigned)((int)x.y & 0xF)) << 4;
    r |= ((unsigned)((int)x.z & 0xF)) << 8;
    r |= ((unsigned)((int)x.w & 0xF)) << 12;
    r |= ((unsigned)((int)y.x & 0xF)) << 16;
    r |= ((unsigned)((int)y.y & 0xF)) << 20;
    r |= ((unsigned)((int)y.z & 0xF)) << 24;
    r |= ((unsigned)((int)y.w & 0xF)) << 28;
    return r;
}

// ---------------- kernel: convert addresses fp32 -> s4 fragment layout ----------------
// grid = NROWPAD blocks (one address row each), 128 threads (one 8-elem nibble-word each)
__global__ void conva_kernel(const float* __restrict__ A) {
    const int r = blockIdx.x;        // address row (incl. zero padding rows)
    const int w = threadIdx.x;       // nibble-word 0..127 (8 k-elems each)
    unsigned pk = 0;
    if (r < NA) {
        const float4* row = reinterpret_cast<const float4*>(A) + (size_t)r * 256;
        float4 v0 = row[2 * w];
        float4 v1 = row[2 * w + 1];
        pk = pack8(v0, v1);
    }
    // m16n8k64 A fragment: row = (lane>>2) + (reg&1)*8 ; k = ks*64 + (lane&3)*8 + (reg>>1)*32 + j
    const int mt = r >> 4, ks = w >> 3, wk = w & 7;
    const int lane = ((r & 7) << 2) | (wk & 3);
    const int reg  = ((wk >> 2) << 1) | ((r & 15) >> 3);
    g_afrag[((((mt * NKS) + ks) * 32 + lane) << 2) + reg] = pk;
}

// ---------------- kernel: convert queries fp32 -> s4 fragment layout ----------------
__global__ void convb_kernel(const float* __restrict__ Q) {
    const int r = blockIdx.x;        // query row 0..511
    const int w = threadIdx.x;       // nibble-word 0..127
    const float4* row = reinterpret_cast<const float4*>(Q) + (size_t)r * 256;
    unsigned pk = pack8(row[2 * w], row[2 * w + 1]);
    // m16n8k64 B fragment: n = lane>>2 ; k = ks*64 + (lane&3)*8 + rb*32 + j
    const int nt = r >> 3, p = nt >> 1, ks = w >> 3, wk = w & 7;
    const int lane = ((r & 7) << 2) | (wk & 3);
    const int reg  = ((nt & 1) << 1) | (wk >> 2);     // [b-half-of-pair][rb]
    g_bfrag[((((p * NKS) + ks) * 32 + lane) << 2) + reg] = pk;
}

// ---------------- kernel: zero output + pair counter ----------------
__global__ void zero_kernel(float* __restrict__ out) {
    int i = blockIdx.x * blockDim.x + threadIdx.x;
    out[i] = 0.0f;
    if (i == 0) g_npairs = 0u;
}

// ---------------- kernel: int4 similarity GEMM + threshold + compaction ----------------
// CTA: 128 M x 256 N. 8 warps = 2(M) x 4(N) of 64x64 warptiles.
__global__ __launch_bounds__(256, 1) void gemm_kernel(const int* __restrict__ thrp) {
    const int tid = threadIdx.x, lane = tid & 31, wid = tid >> 5;
    const int cta = blockIdx.x;
    const int mtile_base = (cta >> 1) * 8 + (wid & 1) * 4;   // 4 m16 tiles per warp
    const int pass = cta & 1;
    const int nt_base = pass * 32 + (wid >> 1) * 8;          // 8 n8 tiles per warp
    const int p_base = nt_base >> 1;                          // 4 B-pairs per warp

    int acc[4][8][4];
    #pragma unroll
    for (int mi = 0; mi < 4; mi++)
        #pragma unroll
        for (int ni = 0; ni < 8; ni++)
            #pragma unroll
            for (int rr = 0; rr < 4; rr++) acc[mi][ni][rr] = 0;

    const uint4* __restrict__ ab = reinterpret_cast<const uint4*>(g_afrag);
    const uint4* __restrict__ bb = reinterpret_cast<const uint4*>(g_bfrag);

    uint4 a[4], b[4];
    #pragma unroll
    for (int i = 0; i < 4; i++) a[i] = ab[((mtile_base + i) * NKS + 0) * 32 + lane];
    #pragma unroll
    for (int i = 0; i < 4; i++) b[i] = bb[((p_base + i) * NKS + 0) * 32 + lane];

    #pragma unroll 1
    for (int ks = 0; ks < NKS; ks++) {
        uint4 an[4], bn[4];
        const int ksn = (ks < NKS - 1) ? ks + 1 : NKS - 1;
        #pragma unroll
        for (int i = 0; i < 4; i++) an[i] = ab[((mtile_base + i) * NKS + ksn) * 32 + lane];
        #pragma unroll
        for (int i = 0; i < 4; i++) bn[i] = bb[((p_base + i) * NKS + ksn) * 32 + lane];

        #pragma unroll
        for (int mi = 0; mi < 4; mi++)
            #pragma unroll
            for (int pi = 0; pi < 4; pi++) {
                imma(acc[mi][2 * pi],     a[mi], b[pi].x, b[pi].y);
                imma(acc[mi][2 * pi + 1], a[mi], b[pi].z, b[pi].w);
            }
        #pragma unroll
        for (int i = 0; i < 4; i++) { a[i] = an[i]; b[i] = bn[i]; }
    }

    // threshold: robust to int32 or float32 payload
    int tb = *thrp;
    const int thr = (tb > -1000000 && tb < 1000000) ? tb : (int)__int_as_float(tb);

    // epilogue: c0: row=lane/4, col=(lane%4)*2 ; c1: col+1 ; c2,c3: row+8
    #pragma unroll
    for (int mi = 0; mi < 4; mi++)
        #pragma unroll
        for (int ni = 0; ni < 8; ni++)
            #pragma unroll
            for (int rr = 0; rr < 4; rr++) {
                int v = acc[mi][ni][rr];
                if (v >= thr) {
                    int row = (mtile_base + mi) * 16 + (lane >> 2) + ((rr >> 1) << 3);
                    int q   = (nt_base + ni) * 8 + ((lane & 3) << 1) + (rr & 1);
                    if (row < NA) {
                        unsigned idx = atomicAdd(&g_npairs, 1u);
                        if (idx < PAIR_CAP)
                            g_pairs[idx] = ((unsigned)q << 17) | (unsigned)row;
                    }
                }
            }
}

// ---------------- kernel: scatter content rows of active pairs ----------------
__global__ __launch_bounds__(256) void scatter_kernel(const float* __restrict__ content,
                                                      float* __restrict__ out) {
    unsigned np = g_npairs;
    if (np > PAIR_CAP) np = PAIR_CAP;
    for (unsigned p = blockIdx.x; p < np; p += gridDim.x) {
        unsigned pr = g_pairs[p];
        unsigned q = pr >> 17;
        unsigned n = pr & 0x1FFFFu;
        float4 v = reinterpret_cast<const float4*>(content + (size_t)n * CDIM)[threadIdx.x];
        float* dst = out + (size_t)q * CDIM + threadIdx.x * 4;
        atomicAdd(dst + 0, v.x);
        atomicAdd(dst + 1, v.y);
        atomicAdd(dst + 2, v.z);
        atomicAdd(dst + 3, v.w);
    }
}

// ---------------- kernel: sign in place ----------------
__global__ void sign_kernel(float* __restrict__ out) {
    int i = blockIdx.x * blockDim.x + threadIdx.x;
    float v = out[i];
    out[i] = (v > 0.0f) ? 1.0f : ((v < 0.0f) ? -1.0f : 0.0f);
}

// ---------------- launcher ----------------
extern "C" void kernel_launch(void* const* d_in, const int* in_sizes, int n_in,
                              void* d_out, int out_size) {
    const float* q   = (const float*)d_in[0];   // address    [512,1024]
    const float* A   = (const float*)d_in[1];   // addresses  [100000,1024]
    const float* C   = (const float*)d_in[2];   // content    [100000,1024]
    const int*   thr = (const int*)  d_in[3];   // threshold scalar
    float* out = (float*)d_out;                 // [512,1024] float32

    zero_kernel<<<(NQ * CDIM) / 256, 256>>>(out);
    convb_kernel<<<NQ, 128>>>(q);
    conva_kernel<<<NROWPAD, 128>>>(A);
    gemm_kernel<<<NCTA, 256>>>(thr);
    scatter_kernel<<<2048, 256>>>(C, out);
    sign_kernel<<<(NQ * CDIM) / 256, 256>>>(out);
}

// round 7
// speedup vs baseline: 3.9805x; 3.9805x over previous
#include <cuda_runtime.h>
#include <cstdint>

// ---------------- problem constants ----------------
#define NQ       512          // batch (queries)
#define NA       100000       // number of stored addresses
#define KDIM     1024
#define CDIM     1024
#define NWORDS   32           // 1024 bits / 32
#define ROWS_CTA 128          // address rows per sim CTA
#define NCTA_SIM 782          // ceil(NA/128)
#define PAIR_CAP (1u<<20)
#define QBYTES   (NQ * NWORDS * 4)   // 64 KB

// ---------------- device globals (static, no runtime alloc) ----------------
__device__ unsigned g_qbits[NQ * NWORDS];   // bit-packed queries
__device__ unsigned g_npairs;
__device__ unsigned g_pairs[PAIR_CAP];

// carry-save adder: acc' = sum bit, returns carry word (2 LOP3)
__device__ __forceinline__ unsigned csa(unsigned& acc, unsigned a, unsigned b) {
    unsigned s = acc ^ a ^ b;
    unsigned c = (acc & a) | ((acc ^ a) & b);   // majority
    acc = s;
    return c;
}

// ---------------- kernel: bit-pack queries (ballot permutation) ----------------
// 4 CTAs x 128 threads; each warp packs 32 query rows cooperatively.
__global__ void convb_kernel(const float* __restrict__ Q) {
    const int lane = threadIdx.x & 31, wwid = threadIdx.x >> 5;
    const int rbase = blockIdx.x * 128 + wwid * 32;
    unsigned aw[NWORDS];
    #pragma unroll
    for (int w = 0; w < NWORDS; w++) aw[w] = 0u;

    for (int i = 0; i < 32; i++) {
        const int row = rbase + i;
        const float4* rp = reinterpret_cast<const float4*>(Q) + (size_t)row * 256;
        #pragma unroll
        for (int c = 0; c < 8; c++) {
            float4 f = rp[c * 32 + lane];
            unsigned b0 = __ballot_sync(0xFFFFFFFFu, f.x < 0.0f);
            unsigned b1 = __ballot_sync(0xFFFFFFFFu, f.y < 0.0f);
            unsigned b2 = __ballot_sync(0xFFFFFFFFu, f.z < 0.0f);
            unsigned b3 = __ballot_sync(0xFFFFFFFFu, f.w < 0.0f);
            if (lane == i) {
                aw[c * 4 + 0] = b0; aw[c * 4 + 1] = b1;
                aw[c * 4 + 2] = b2; aw[c * 4 + 3] = b3;
            }
        }
    }
    const int row = rbase + lane;
    #pragma unroll
    for (int w = 0; w < NWORDS; w++) g_qbits[row * NWORDS + w] = aw[w];
}

// ---------------- kernel: zero output + pair counter ----------------
__global__ void zero_kernel(float* __restrict__ out) {
    int i = blockIdx.x * blockDim.x + threadIdx.x;
    out[i] = 0.0f;
    if (i == 0) g_npairs = 0u;
}

// ---------------- kernel: popcount similarity + threshold + compaction ----------------
// grid = 782, 128 threads. Each thread owns one address row (packed in regs);
// all 512 queries live bit-packed in 64KB smem.
__global__ __launch_bounds__(128, 3) void sim_kernel(const float* __restrict__ A,
                                                     const int* __restrict__ thrp) {
    extern __shared__ unsigned qs[];   // [NQ][NWORDS] = 64 KB

    const int tid = threadIdx.x, lane = tid & 31, wwid = tid >> 5;

    // stage queries global -> smem (vectorized)
    {
        const uint4* src = reinterpret_cast<const uint4*>(g_qbits);
        uint4* dst = reinterpret_cast<uint4*>(qs);
        #pragma unroll
        for (int i = 0; i < QBYTES / 16 / 128; i++) dst[tid + 128 * i] = src[tid + 128 * i];
    }

    // cooperative load + ballot-pack this warp's 32 address rows
    const int rbase = blockIdx.x * ROWS_CTA + wwid * 32;
    unsigned aw[NWORDS];
    #pragma unroll
    for (int w = 0; w < NWORDS; w++) aw[w] = 0u;

    for (int i = 0; i < 32; i++) {
        const int row = rbase + i;
        if (row >= NA) break;   // uniform per iteration within warp
        const float4* rp = reinterpret_cast<const float4*>(A) + (size_t)row * 256;
        #pragma unroll
        for (int c = 0; c < 8; c++) {
            float4 f = rp[c * 32 + lane];
            unsigned b0 = __ballot_sync(0xFFFFFFFFu, f.x < 0.0f);
            unsigned b1 = __ballot_sync(0xFFFFFFFFu, f.y < 0.0f);
            unsigned b2 = __ballot_sync(0xFFFFFFFFu, f.z < 0.0f);
            unsigned b3 = __ballot_sync(0xFFFFFFFFu, f.w < 0.0f);
            if (lane == i) {
                aw[c * 4 + 0] = b0; aw[c * 4 + 1] = b1;
                aw[c * 4 + 2] = b2; aw[c * 4 + 3] = b3;
            }
        }
    }
    __syncthreads();

    // threshold: robust to int32 or float32 payload; sim >= thr  <=>  hamming <= hlim
    int tb = *thrp;
    const int thr = (tb > -1000000 && tb < 1000000) ? tb : (int)__int_as_float(tb);
    const int hlim = (KDIM - thr) >> 1;

    const int myrow = rbase + lane;
    if (myrow < NA) {
        #pragma unroll 1
        for (int q = 0; q < NQ; q++) {
            const uint4* qp = reinterpret_cast<const uint4*>(qs + q * NWORDS);
            unsigned ones = 0, twos = 0, fours = 0;
            int h8 = 0;
            #pragma unroll
            for (int g = 0; g < 4; g++) {
                uint4 qa = qp[2 * g], qb = qp[2 * g + 1];
                unsigned x0 = aw[8 * g + 0] ^ qa.x;
                unsigned x1 = aw[8 * g + 1] ^ qa.y;
                unsigned x2 = aw[8 * g + 2] ^ qa.z;
                unsigned x3 = aw[8 * g + 3] ^ qa.w;
                unsigned x4 = aw[8 * g + 4] ^ qb.x;
                unsigned x5 = aw[8 * g + 5] ^ qb.y;
                unsigned x6 = aw[8 * g + 6] ^ qb.z;
                unsigned x7 = aw[8 * g + 7] ^ qb.w;
                unsigned t1 = csa(ones, x0, x1);
                unsigned t2 = csa(ones, x2, x3);
                unsigned f1 = csa(twos, t1, t2);
                t1 = csa(ones, x4, x5);
                t2 = csa(ones, x6, x7);
                unsigned f2 = csa(twos, t1, t2);
                unsigned e  = csa(fours, f1, f2);
                h8 += __popc(e);
            }
            int h = 8 * h8 + 4 * __popc(fours) + 2 * __popc(twos) + __popc(ones);
            if (h <= hlim) {
                unsigned idx = atomicAdd(&g_npairs, 1u);
                if (idx < PAIR_CAP)
                    g_pairs[idx] = ((unsigned)q << 17) | (unsigned)myrow;
            }
        }
    }
}

// ---------------- kernel: scatter content rows of active pairs ----------------
__global__ __launch_bounds__(256) void scatter_kernel(const float* __restrict__ content,
                                                      float* __restrict__ out) {
    unsigned np = g_npairs;
    if (np > PAIR_CAP) np = PAIR_CAP;
    for (unsigned p = blockIdx.x; p < np; p += gridDim.x) {
        unsigned pr = g_pairs[p];
        unsigned q = pr >> 17;
        unsigned n = pr & 0x1FFFFu;
        float4 v = reinterpret_cast<const float4*>(content + (size_t)n * CDIM)[threadIdx.x];
        float* dst = out + (size_t)q * CDIM + threadIdx.x * 4;
        atomicAdd(dst + 0, v.x);
        atomicAdd(dst + 1, v.y);
        atomicAdd(dst + 2, v.z);
        atomicAdd(dst + 3, v.w);
    }
}

// ---------------- kernel: sign in place ----------------
__global__ void sign_kernel(float* __restrict__ out) {
    int i = blockIdx.x * blockDim.x + threadIdx.x;
    float v = out[i];
    out[i] = (v > 0.0f) ? 1.0f : ((v < 0.0f) ? -1.0f : 0.0f);
}

// ---------------- launcher ----------------
extern "C" void kernel_launch(void* const* d_in, const int* in_sizes, int n_in,
                              void* d_out, int out_size) {
    const float* q   = (const float*)d_in[0];   // address    [512,1024]
    const float* A   = (const float*)d_in[1];   // addresses  [100000,1024]
    const float* C   = (const float*)d_in[2];   // content    [100000,1024]
    const int*   thr = (const int*)  d_in[3];   // threshold scalar
    float* out = (float*)d_out;                 // [512,1024] float32

    static bool once = []() {
        cudaFuncSetAttribute(sim_kernel,
                             cudaFuncAttributeMaxDynamicSharedMemorySize, QBYTES);
        return true;
    }();
    (void)once;

    zero_kernel<<<(NQ * CDIM) / 256, 256>>>(out);
    convb_kernel<<<4, 128>>>(q);
    sim_kernel<<<NCTA_SIM, 128, QBYTES>>>(A, thr);
    scatter_kernel<<<2048, 256>>>(C, out);
    sign_kernel<<<(NQ * CDIM) / 256, 256>>>(out);
}